// round 14
// baseline (speedup 1.0000x reference)
#include <cuda_runtime.h>
#include <cuda_bf16.h>

#define T_STEPS 1024
#define BATCH   256
#define HID     512
#define NBLK    128
#define THREADS 512

// 2D tiling: 4 batch-slices x 32 unit-slices
#define MB       64      // batches per block
#define NG       64      // gate columns per block (16 units x 4 gates)
#define UNITS    16

// W smem (k-major, proven layout)
#define WPITCH    72                          // bf16 per k-row (64 + 8 pad) = 144 B
#define WBYTES    (HID * WPITCH * 2)          // 73728 per W matrix
#define OFF_WHI   0
#define OFF_WLO   WBYTES
#define OFF_P     (2 * WBYTES)                // 147456 (params, 1 KB)
#define OFF_R     (OFF_P + 1024)              // 148480 (reduction buffer)
#define RED_BYTES (4 * 4 * 8 * 32 * 16)       // 65536: [wm][slot][n8][lane] float4
#define SMEM_TOTAL (OFF_R + RED_BYTES)        // 214016

// h in MMA A-fragment layout, hi and lo split (proven r12/r13):
// [buf][mi][mt][kt][lane][8 bf16] -> 16B lane record; warp kt-load = 512B contig.
__device__ __nv_bfloat16 g_hfhi[2][4][4][32][32][8];   // 512 KB
__device__ __nv_bfloat16 g_hflo[2][4][4][32][32][8];   // 512 KB
__device__ float g_hplain[BATCH * HID];                // final h, fp32
__device__ float g_zxT[64 * BATCH];
__device__ float g_zeT[16 * BATCH];
__device__ unsigned int g_gc[4][128];      // [leaf][mi*32] spread group counters
__device__ unsigned int g_fcnt;            // full-grid monotonic counter

// ---------- helpers ----------
__device__ __forceinline__ unsigned s2u(const void* p) {
    unsigned r;
    asm("{ .reg .u64 t; cvta.to.shared.u64 t, %1; cvt.u32.u64 %0, t; }"
        : "=r"(r) : "l"(p));
    return r;
}

__device__ __forceinline__ void mma16816(float* d, const unsigned* a, const unsigned* b) {
    asm volatile(
        "mma.sync.aligned.m16n8k16.row.col.f32.bf16.bf16.f32 "
        "{%0,%1,%2,%3}, {%4,%5,%6,%7}, {%8,%9}, {%0,%1,%2,%3};"
        : "+f"(d[0]), "+f"(d[1]), "+f"(d[2]), "+f"(d[3])
        : "r"(a[0]), "r"(a[1]), "r"(a[2]), "r"(a[3]), "r"(b[0]), "r"(b[1]));
}

__device__ __forceinline__ void ldsm_x4t(unsigned* r, unsigned addr) {
    asm volatile("ldmatrix.sync.aligned.m8n8.x4.trans.shared.b16 {%0,%1,%2,%3}, [%4];"
                 : "=r"(r[0]), "=r"(r[1]), "=r"(r[2]), "=r"(r[3]) : "r"(addr));
}

__device__ __forceinline__ float sigf(float v) {
    return __fdividef(1.0f, 1.0f + __expf(-v));
}
__device__ __forceinline__ float tanh_fast(float v) {
    return __fdividef(2.0f, 1.0f + __expf(-2.0f * v)) - 1.0f;
}

// Spread group barrier: 4 leaf counters (8 arrivals each), parallel 4-lane poll.
__device__ __forceinline__ void gsyncG(int mi, int ni, unsigned gep,
                                       int tid, int lane) {
    __syncthreads();
    if (tid == 0) {
        __threadfence();
        asm volatile("red.release.gpu.global.add.u32 [%0], 1;"
                     :: "l"(&g_gc[ni & 3][mi << 5]) : "memory");
    }
    const unsigned target = 8u * gep;
    bool pend = (lane < 4);
    unsigned int* addr = &g_gc[lane & 3][mi << 5];
    while (__any_sync(0xffffffffu, pend)) {
        if (pend) {
            unsigned v;
            asm volatile("ld.acquire.gpu.global.u32 %0, [%1];"
                         : "=r"(v) : "l"(addr) : "memory");
            pend = (v < target);
        }
    }
    __syncwarp();
}

// Full-grid monotonic barrier (3 uses at end).
__device__ __forceinline__ void arrive_wait(unsigned int* cnt, unsigned target,
                                            int tid, int lane) {
    __syncthreads();
    if (tid == 0) {
        __threadfence();
        asm volatile("red.release.gpu.global.add.u32 [%0], 1;"
                     :: "l"(cnt) : "memory");
    }
    if (lane == 0) {
        unsigned v;
        do {
            asm volatile("ld.acquire.gpu.global.u32 %0, [%1];"
                         : "=r"(v) : "l"(cnt) : "memory");
        } while (v < target);
    }
    __syncwarp();
}

// ---------- main persistent kernel ----------
extern "C" __global__ void __launch_bounds__(THREADS, 1)
lstm_persist(const float* __restrict__ x, const float* __restrict__ a,
             const float* __restrict__ y,
             const float* __restrict__ W_ih, const float* __restrict__ W_hh,
             const float* __restrict__ b_ih, const float* __restrict__ b_hh,
             const float* __restrict__ W_eta, const float* __restrict__ b_eta,
             const float* __restrict__ W_xi,  const float* __restrict__ b_xi,
             const float* __restrict__ W_zeta, const float* __restrict__ b_zeta,
             float* __restrict__ out) {
    extern __shared__ char smem[];
    __nv_bfloat16* sWhi = (__nv_bfloat16*)(smem + OFF_WHI);
    __nv_bfloat16* sWlo = (__nv_bfloat16*)(smem + OFF_WLO);
    float* swx = (float*)(smem + OFF_P);
    float* swa = swx + 64;
    float* swy = swx + 128;
    float* sbb = swx + 192;
    float4* sv = (float4*)(smem + OFF_R);   // [wm][slot][n8][lane]
    const unsigned sb = s2u(smem);

    const int tid  = threadIdx.x;
    const int lane = tid & 31;
    const int w    = tid >> 5;       // 16 warps
    const int bid  = blockIdx.x;
    const int mi   = bid >> 5;       // batch slice 0..3
    const int ni   = bid & 31;       // unit slice 0..31
    const int wm   = w & 3;          // m-tile (== SMSP id)
    const int kq   = w >> 2;         // kt quarter 0..3 (also owns n8 {2kq,2kq+1})

    unsigned gep = 0;

    // ---- W tile into smem, K-MAJOR (proven layout) ----
    for (int idx = tid; idx < NG * HID; idx += THREADS) {
        int j = idx >> 9, k = idx & 511;
        int row = (j & 3) * HID + ni * UNITS + (j >> 2);
        float v = W_hh[row * HID + k];
        __nv_bfloat16 hi = __float2bfloat16(v);
        sWhi[k * WPITCH + j] = hi;
        sWlo[k * WPITCH + j] = __float2bfloat16(v - __bfloat162float(hi));
    }
    if (tid < NG) {
        int row = (tid & 3) * HID + ni * UNITS + (tid >> 2);
        swx[tid] = W_ih[row * 3 + 0];
        swa[tid] = W_ih[row * 3 + 1];
        swy[tid] = W_ih[row * 3 + 2];
        sbb[tid] = b_ih[row] + b_hh[row];
    }

    // ---- zero fragment buffer 0 for our batch slice (group-cooperative) ----
    {
        uint4 z = make_uint4(0u, 0u, 0u, 0u);
        uint4* Zh = (uint4*)(&g_hfhi[0][mi][0][0][0][0]);   // 4096 uint4
        uint4* Zl = (uint4*)(&g_hflo[0][mi][0][0][0][0]);
        for (int i = ni * THREADS + tid; i < 4096; i += 32 * THREADS) {
            Zh[i] = z;
            Zl[i] = z;
        }
    }
    gsyncG(mi, ni, ++gep, tid, lane);

    // epilogue ownership: warp (wm,kq) finalizes n8 in {2kq, 2kq+1}
    const bool act = ((lane & 1) == 0);
    const int qr  = lane >> 2;              // 0..7
    const int hb  = (lane & 3) >> 1;        // unit low bit
    const int r0  = 16 * wm + qr;
    const int b0g = mi * MB + r0;
    const int b1g = b0g + 8;
    float cst[2][2];
    cst[0][0] = cst[0][1] = cst[1][0] = cst[1][1] = 0.f;

    // B ldmatrix base
    const unsigned bbase = (unsigned)((lane & 15) * (WPITCH * 2)
                                      + ((lane >> 4) & 1) * 16);

    int cur = 0;
    for (int s = 0; s < T_STEPS; s++) {
        const int t = T_STEPS - 1 - s;

        // A fragments for this warp's kt quarter, straight from global.
        const uint4* Ah = (const uint4*)(&g_hfhi[cur][mi][wm][kq * 8][lane][0]);
        const uint4* Al = (const uint4*)(&g_hflo[cur][mi][wm][kq * 8][lane][0]);

        // depth-2 prefetch ring over 8 kt
        uint4 rh[2], rl[2];
        rh[0] = __ldcg(Ah);      rl[0] = __ldcg(Al);
        rh[1] = __ldcg(Ah + 32); rl[1] = __ldcg(Al + 32);

        // epilogue inputs (all warps; same addrs per SMSP -> cached)
        float x0 = __ldg(&x[t * BATCH + b0g]);
        float a0 = __ldg(&a[t * BATCH + b0g]);
        float y0 = __ldg(&y[t * BATCH + b0g]);
        float x1 = __ldg(&x[t * BATCH + b1g]);
        float a1 = __ldg(&a[t * BATCH + b1g]);
        float y1 = __ldg(&y[t * BATCH + b1g]);

        float acc[8][4];
        #pragma unroll
        for (int i = 0; i < 8; i++)
            #pragma unroll
            for (int jj = 0; jj < 4; jj++) acc[i][jj] = 0.f;

        #pragma unroll
        for (int kl = 0; kl < 8; kl++) {
            const int kt = kq * 8 + kl;
            const int slot = kl & 1;
            unsigned ahi[4], alo[4];
            { uint4 v = rh[slot]; ahi[0]=v.x; ahi[1]=v.y; ahi[2]=v.z; ahi[3]=v.w; }
            { uint4 v = rl[slot]; alo[0]=v.x; alo[1]=v.y; alo[2]=v.z; alo[3]=v.w; }
            if (kl + 2 < 8) {
                rh[slot] = __ldcg(Ah + (kl + 2) * 32);
                rl[slot] = __ldcg(Al + (kl + 2) * 32);
            }

            const unsigned krow = (unsigned)(kt * (16 * WPITCH * 2));
            #pragma unroll
            for (int ng = 0; ng < 4; ng++) {
                unsigned bhi[4], blo[4];
                const unsigned boff = krow + bbase + (unsigned)(ng * 32);
                ldsm_x4t(bhi, sb + OFF_WHI + boff);
                ldsm_x4t(blo, sb + OFF_WLO + boff);
                mma16816(acc[2*ng],     ahi, bhi + 0);
                mma16816(acc[2*ng + 1], ahi, bhi + 2);
                mma16816(acc[2*ng],     ahi, blo + 0);
                mma16816(acc[2*ng + 1], ahi, blo + 2);
                mma16816(acc[2*ng],     alo, bhi + 0);
                mma16816(acc[2*ng + 1], alo, bhi + 2);
            }
        }

        // ---- all-warp reduction: publish non-owned n8 partials (6 STS.128) ----
        {
            float4* wslot = sv + ((wm * 4 + kq) * 8) * 32 + lane;
            #pragma unroll
            for (int n8 = 0; n8 < 8; n8++) {
                if ((n8 >> 1) == kq) continue;   // own groups stay in regs
                wslot[n8 * 32] =
                    make_float4(acc[n8][0], acc[n8][1], acc[n8][2], acc[n8][3]);
            }
        }
        __syncthreads();

        // fold 3 other slots for our 2 owned n8 groups (6 LDS.128)
        #pragma unroll
        for (int j = 0; j < 2; j++) {
            const int n8 = 2 * kq + j;
            #pragma unroll
            for (int sl = 0; sl < 4; sl++) {
                if (sl == kq) continue;
                float4 v = sv[(((wm * 4 + sl) * 8) + n8) * 32 + lane];
                acc[n8][0] += v.x; acc[n8][1] += v.y;
                acc[n8][2] += v.z; acc[n8][3] += v.w;
            }
        }

        // ---- epilogue for owned n8 groups: xproj, exchange, gates, h store ----
        char* Hh = (char*)(&g_hfhi[cur ^ 1][mi][wm][ni][0][0]);
        char* Hl = (char*)(&g_hflo[cur ^ 1][mi][wm][ni][0][0]);
        #pragma unroll
        for (int j = 0; j < 2; j++) {
            const int n8 = 2 * kq + j;
            int ce = n8 * 8 + 2 * (lane & 3);
            int co = ce + 1;
            float wxe = swx[ce], wae = swa[ce], wye = swy[ce], bbe = sbb[ce];
            float wxo = swx[co], wao = swa[co], wyo = swy[co], bbo = sbb[co];
            acc[n8][0] += fmaf(wxe, x0, fmaf(wae, a0, fmaf(wye, y0, bbe)));
            acc[n8][1] += fmaf(wxo, x0, fmaf(wao, a0, fmaf(wyo, y0, bbo)));
            acc[n8][2] += fmaf(wxe, x1, fmaf(wae, a1, fmaf(wye, y1, bbe)));
            acc[n8][3] += fmaf(wxo, x1, fmaf(wao, a1, fmaf(wyo, y1, bbo)));

            float gg[4];
            #pragma unroll
            for (int i = 0; i < 4; i++)
                gg[i] = __shfl_xor_sync(0xffffffffu, acc[n8][i], 1);

            if (act) {
                const int flane = qr * 4 + (n8 & 3);
                const int regbase = 2 * (n8 >> 2);
                #pragma unroll
                for (int rr = 0; rr < 2; rr++) {
                    float iv = acc[n8][2 * rr + 0];
                    float fv = acc[n8][2 * rr + 1];
                    float gv = gg[2 * rr + 0];
                    float ov = gg[2 * rr + 1];
                    float cn = sigf(fv) * cst[j][rr] + sigf(iv) * tanh_fast(gv);
                    cst[j][rr] = cn;
                    float h = sigf(ov) * tanh_fast(cn);
                    unsigned off = (unsigned)(flane * 16 + (regbase + rr) * 4 + hb * 2);
                    __nv_bfloat16 hh = __float2bfloat16(h);
                    *(__nv_bfloat16*)(Hh + off) = hh;
                    *(__nv_bfloat16*)(Hl + off) =
                        __float2bfloat16(h - __bfloat162float(hh));
                    if (s == T_STEPS - 1) {
                        int kg = ni * UNITS + 2 * n8 + hb;
                        int bg = rr ? b1g : b0g;
                        g_hplain[bg * HID + kg] = h;
                    }
                }
            }
        }
        gsyncG(mi, ni, ++gep, tid, lane);
        cur ^= 1;
    }

    // all four groups done before heads read full h
    arrive_wait(&g_fcnt, 128u, tid, lane);

    const int b = tid;

    // Phase A: zx columns (blocks 0..63), ze logits (blocks 64..79)
    if (b < BATCH) {
        if (bid < 64) {
            const int m = bid;
            float acc = b_xi[m];
            const float* wm_ = W_xi + m * HID;
            #pragma unroll 8
            for (int k = 0; k < HID; k++)
                acc = fmaf(g_hplain[b * HID + k], __ldg(&wm_[k]), acc);
            out[b * 64 + m] = acc;                  // zx: [B][64] at 0
            g_zxT[m * BATCH + b] = acc;
        } else if (bid < 80) {
            const int e = bid - 64;
            float acc = b_eta[e];
            const float* we = W_eta + e * HID;
            #pragma unroll 8
            for (int k = 0; k < HID; k++)
                acc = fmaf(g_hplain[b * HID + k], __ldg(&we[k]), acc);
            g_zeT[e * BATCH + b] = acc;
        }
    }
    arrive_wait(&g_fcnt, 256u, tid, lane);

    // Phase B: zy columns (blocks 0..63), ze softmax (block 64)
    if (b < BATCH) {
        if (bid < 64) {
            const int m = bid;
            float acc = b_zeta[m];
            const float* wz = W_zeta + m * (HID + 64);
            #pragma unroll 8
            for (int k = 0; k < HID; k++)
                acc = fmaf(g_hplain[b * HID + k], __ldg(&wz[k]), acc);
            #pragma unroll
            for (int j = 0; j < 64; j++)
                acc = fmaf(g_zxT[j * BATCH + b], __ldg(&wz[HID + j]), acc);
            out[16384 + b * 64 + m] = acc;          // zy: [B][64] at 16384
        } else if (bid == 64) {
            float l[16];
            float mx = -1e30f;
            #pragma unroll
            for (int e = 0; e < 16; e++) {
                l[e] = g_zeT[e * BATCH + b];
                mx = fmaxf(mx, l[e]);
            }
            float ssum = 0.0f;
            #pragma unroll
            for (int e = 0; e < 16; e++) { l[e] = __expf(l[e] - mx); ssum += l[e]; }
            float inv = __fdividef(1.0f, ssum);
            #pragma unroll
            for (int e = 0; e < 16; e++)
                out[32768 + b * 16 + e] = l[e] * inv;   // ze: [B][16] at 32768
        }
    }
}

// Reset barrier counters after each run so graph replays start from zero.
extern "C" __global__ void reset_counters() {
    int i = threadIdx.x;
    if (i < 512) ((unsigned int*)g_gc)[i] = 0u;
    if (i == 0) g_fcnt = 0u;
}

extern "C" void kernel_launch(void* const* d_in, const int* in_sizes, int n_in,
                              void* d_out, int out_size) {
    const float* x      = (const float*)d_in[0];
    const float* a      = (const float*)d_in[1];
    const float* y      = (const float*)d_in[2];
    const float* W_ih   = (const float*)d_in[3];
    const float* W_hh   = (const float*)d_in[4];
    const float* b_ih   = (const float*)d_in[5];
    const float* b_hh   = (const float*)d_in[6];
    const float* W_eta  = (const float*)d_in[7];
    const float* b_eta  = (const float*)d_in[8];
    const float* W_xi   = (const float*)d_in[9];
    const float* b_xi   = (const float*)d_in[10];
    const float* W_zeta = (const float*)d_in[11];
    const float* b_zeta = (const float*)d_in[12];

    cudaFuncSetAttribute(lstm_persist,
                         cudaFuncAttributeMaxDynamicSharedMemorySize, SMEM_TOTAL);
    lstm_persist<<<NBLK, THREADS, SMEM_TOTAL>>>(
        x, a, y, W_ih, W_hh, b_ih, b_hh,
        W_eta, b_eta, W_xi, b_xi, W_zeta, b_zeta,
        (float*)d_out);
    reset_counters<<<1, 512>>>();
}

// round 15
// speedup vs baseline: 1.0472x; 1.0472x over previous
#include <cuda_runtime.h>
#include <cuda_bf16.h>

#define T_STEPS 1024
#define BATCH   256
#define HID     512
#define NBLK    128
#define THREADS 512

// 2D tiling: 4 batch-slices x 32 unit-slices
#define MB       64      // batches per block
#define NG       64      // gate columns per block (16 units x 4 gates)
#define UNITS    16

// W smem (k-major, proven layout)
#define WPITCH    72                          // bf16 per k-row (64 + 8 pad) = 144 B
#define WBYTES    (HID * WPITCH * 2)          // 73728 per W matrix
#define OFF_WHI   0
#define OFF_WLO   WBYTES
#define OFF_P     (2 * WBYTES)                // 147456 (params, 1 KB)
#define OFF_R     (OFF_P + 1024)              // 148480 (reduction buffer)
#define RED_BYTES (4 * 4 * 8 * 32 * 16)       // 65536: [wm][slot][n8][lane] float4
#define SMEM_TOTAL (OFF_R + RED_BYTES)        // 214016

// h in MMA A-fragment layout, hi and lo split (proven r12/r13):
// [buf][mi][mt][kt][lane][8 bf16] -> 16B lane record; warp kt-load = 512B contig.
__device__ __nv_bfloat16 g_hfhi[2][4][4][32][32][8];   // 512 KB
__device__ __nv_bfloat16 g_hflo[2][4][4][32][32][8];   // 512 KB
__device__ float g_hplain[BATCH * HID];                // final h, fp32
__device__ float g_zxT[64 * BATCH];
__device__ float g_zeT[16 * BATCH];
__device__ unsigned int g_gc[4][128];      // [leaf][mi*32] spread group counters
__device__ unsigned int g_fcnt;            // full-grid monotonic counter

// ---------- helpers ----------
__device__ __forceinline__ unsigned s2u(const void* p) {
    unsigned r;
    asm("{ .reg .u64 t; cvta.to.shared.u64 t, %1; cvt.u32.u64 %0, t; }"
        : "=r"(r) : "l"(p));
    return r;
}

__device__ __forceinline__ void mma16816(float* d, const unsigned* a, const unsigned* b) {
    asm volatile(
        "mma.sync.aligned.m16n8k16.row.col.f32.bf16.bf16.f32 "
        "{%0,%1,%2,%3}, {%4,%5,%6,%7}, {%8,%9}, {%0,%1,%2,%3};"
        : "+f"(d[0]), "+f"(d[1]), "+f"(d[2]), "+f"(d[3])
        : "r"(a[0]), "r"(a[1]), "r"(a[2]), "r"(a[3]), "r"(b[0]), "r"(b[1]));
}

__device__ __forceinline__ void ldsm_x4t(unsigned* r, unsigned addr) {
    asm volatile("ldmatrix.sync.aligned.m8n8.x4.trans.shared.b16 {%0,%1,%2,%3}, [%4];"
                 : "=r"(r[0]), "=r"(r[1]), "=r"(r[2]), "=r"(r[3]) : "r"(addr));
}

__device__ __forceinline__ float sigf(float v) {
    return __fdividef(1.0f, 1.0f + __expf(-v));
}
__device__ __forceinline__ float tanh_fast(float v) {
    return __fdividef(2.0f, 1.0f + __expf(-2.0f * v)) - 1.0f;
}

// Spread group barrier: 4 leaf counters (8 arrivals each), parallel 4-lane poll.
__device__ __forceinline__ void gsyncG(int mi, int ni, unsigned gep,
                                       int tid, int lane) {
    __syncthreads();
    if (tid == 0) {
        __threadfence();
        asm volatile("red.release.gpu.global.add.u32 [%0], 1;"
                     :: "l"(&g_gc[ni & 3][mi << 5]) : "memory");
    }
    const unsigned target = 8u * gep;
    bool pend = (lane < 4);
    unsigned int* addr = &g_gc[lane & 3][mi << 5];
    while (__any_sync(0xffffffffu, pend)) {
        if (pend) {
            unsigned v;
            asm volatile("ld.acquire.gpu.global.u32 %0, [%1];"
                         : "=r"(v) : "l"(addr) : "memory");
            pend = (v < target);
        }
    }
    __syncwarp();
}

// Full-grid monotonic barrier (3 uses at end).
__device__ __forceinline__ void arrive_wait(unsigned int* cnt, unsigned target,
                                            int tid, int lane) {
    __syncthreads();
    if (tid == 0) {
        __threadfence();
        asm volatile("red.release.gpu.global.add.u32 [%0], 1;"
                     :: "l"(cnt) : "memory");
    }
    if (lane == 0) {
        unsigned v;
        do {
            asm volatile("ld.acquire.gpu.global.u32 %0, [%1];"
                         : "=r"(v) : "l"(cnt) : "memory");
        } while (v < target);
    }
    __syncwarp();
}

// ---------- main persistent kernel ----------
extern "C" __global__ void __launch_bounds__(THREADS, 1)
lstm_persist(const float* __restrict__ x, const float* __restrict__ a,
             const float* __restrict__ y,
             const float* __restrict__ W_ih, const float* __restrict__ W_hh,
             const float* __restrict__ b_ih, const float* __restrict__ b_hh,
             const float* __restrict__ W_eta, const float* __restrict__ b_eta,
             const float* __restrict__ W_xi,  const float* __restrict__ b_xi,
             const float* __restrict__ W_zeta, const float* __restrict__ b_zeta,
             float* __restrict__ out) {
    extern __shared__ char smem[];
    __nv_bfloat16* sWhi = (__nv_bfloat16*)(smem + OFF_WHI);
    __nv_bfloat16* sWlo = (__nv_bfloat16*)(smem + OFF_WLO);
    float* swx = (float*)(smem + OFF_P);
    float* swa = swx + 64;
    float* swy = swx + 128;
    float* sbb = swx + 192;
    float4* sv = (float4*)(smem + OFF_R);   // [wm][slot][n8][lane]
    const unsigned sb = s2u(smem);

    const int tid  = threadIdx.x;
    const int lane = tid & 31;
    const int w    = tid >> 5;       // 16 warps
    const int bid  = blockIdx.x;
    const int mi   = bid >> 5;       // batch slice 0..3
    const int ni   = bid & 31;       // unit slice 0..31
    const int wm   = w & 3;          // m-tile (== SMSP id)
    const int kq   = w >> 2;         // kt quarter 0..3 (also owns n8 {2kq,2kq+1})

    unsigned gep = 0;

    // ---- W tile into smem, K-MAJOR (proven layout) ----
    for (int idx = tid; idx < NG * HID; idx += THREADS) {
        int j = idx >> 9, k = idx & 511;
        int row = (j & 3) * HID + ni * UNITS + (j >> 2);
        float v = W_hh[row * HID + k];
        __nv_bfloat16 hi = __float2bfloat16(v);
        sWhi[k * WPITCH + j] = hi;
        sWlo[k * WPITCH + j] = __float2bfloat16(v - __bfloat162float(hi));
    }
    if (tid < NG) {
        int row = (tid & 3) * HID + ni * UNITS + (tid >> 2);
        swx[tid] = W_ih[row * 3 + 0];
        swa[tid] = W_ih[row * 3 + 1];
        swy[tid] = W_ih[row * 3 + 2];
        sbb[tid] = b_ih[row] + b_hh[row];
    }

    // ---- zero fragment buffer 0 for our batch slice (group-cooperative) ----
    {
        uint4 z = make_uint4(0u, 0u, 0u, 0u);
        uint4* Zh = (uint4*)(&g_hfhi[0][mi][0][0][0][0]);   // 4096 uint4
        uint4* Zl = (uint4*)(&g_hflo[0][mi][0][0][0][0]);
        for (int i = ni * THREADS + tid; i < 4096; i += 32 * THREADS) {
            Zh[i] = z;
            Zl[i] = z;
        }
    }
    gsyncG(mi, ni, ++gep, tid, lane);

    // epilogue ownership: warp (wm,kq) finalizes n8 in {2kq, 2kq+1}
    const bool act = ((lane & 1) == 0);
    const int qr  = lane >> 2;              // 0..7
    const int hb  = (lane & 3) >> 1;        // unit low bit
    const int r0  = 16 * wm + qr;
    const int b0g = mi * MB + r0;
    const int b1g = b0g + 8;
    float cst[2][2];
    cst[0][0] = cst[0][1] = cst[1][0] = cst[1][1] = 0.f;

    // B ldmatrix base
    const unsigned bbase = (unsigned)((lane & 15) * (WPITCH * 2)
                                      + ((lane >> 4) & 1) * 16);

    int cur = 0;
    for (int s = 0; s < T_STEPS; s++) {
        const int t = T_STEPS - 1 - s;

        // A fragments for this warp's kt quarter, straight from global.
        const uint4* Ah = (const uint4*)(&g_hfhi[cur][mi][wm][kq * 8][lane][0]);
        const uint4* Al = (const uint4*)(&g_hflo[cur][mi][wm][kq * 8][lane][0]);

        // depth-2 prefetch ring over 8 kt
        uint4 rh[2], rl[2];
        rh[0] = __ldcg(Ah);      rl[0] = __ldcg(Al);
        rh[1] = __ldcg(Ah + 32); rl[1] = __ldcg(Al + 32);

        float acc[8][4];
        #pragma unroll
        for (int i = 0; i < 8; i++)
            #pragma unroll
            for (int jj = 0; jj < 4; jj++) acc[i][jj] = 0.f;

        #pragma unroll
        for (int kl = 0; kl < 8; kl++) {
            const int kt = kq * 8 + kl;
            const int slot = kl & 1;
            unsigned ahi[4], alo[4];
            { uint4 v = rh[slot]; ahi[0]=v.x; ahi[1]=v.y; ahi[2]=v.z; ahi[3]=v.w; }
            { uint4 v = rl[slot]; alo[0]=v.x; alo[1]=v.y; alo[2]=v.z; alo[3]=v.w; }
            if (kl + 2 < 8) {
                rh[slot] = __ldcg(Ah + (kl + 2) * 32);
                rl[slot] = __ldcg(Al + (kl + 2) * 32);
            }

            const unsigned krow = (unsigned)(kt * (16 * WPITCH * 2));
            #pragma unroll
            for (int ng = 0; ng < 4; ng++) {
                unsigned bhi[4], blo[4];
                const unsigned boff = krow + bbase + (unsigned)(ng * 32);
                ldsm_x4t(bhi, sb + OFF_WHI + boff);
                ldsm_x4t(blo, sb + OFF_WLO + boff);
                mma16816(acc[2*ng],     ahi, bhi + 0);
                mma16816(acc[2*ng + 1], ahi, bhi + 2);
                mma16816(acc[2*ng],     ahi, blo + 0);
                mma16816(acc[2*ng + 1], ahi, blo + 2);
                mma16816(acc[2*ng],     alo, bhi + 0);
                mma16816(acc[2*ng + 1], alo, bhi + 2);
            }
        }

        // ---- all-warp reduction: publish non-owned n8 partials (6 STS.128) ----
        {
            float4* wslot = sv + ((wm * 4 + kq) * 8) * 32 + lane;
            #pragma unroll
            for (int n8 = 0; n8 < 8; n8++) {
                if ((n8 >> 1) == kq) continue;   // own groups stay in regs
                wslot[n8 * 32] =
                    make_float4(acc[n8][0], acc[n8][1], acc[n8][2], acc[n8][3]);
            }
        }

        // epilogue inputs loaded HERE (not live across the GEMM loop; their
        // latency overlaps the syncthreads + fold below)
        float x0 = __ldg(&x[t * BATCH + b0g]);
        float a0 = __ldg(&a[t * BATCH + b0g]);
        float y0 = __ldg(&y[t * BATCH + b0g]);
        float x1 = __ldg(&x[t * BATCH + b1g]);
        float a1 = __ldg(&a[t * BATCH + b1g]);
        float y1 = __ldg(&y[t * BATCH + b1g]);

        __syncthreads();

        // fold 3 other slots for our 2 owned n8 groups (6 LDS.128)
        #pragma unroll
        for (int j = 0; j < 2; j++) {
            const int n8 = 2 * kq + j;
            #pragma unroll
            for (int sl = 0; sl < 4; sl++) {
                if (sl == kq) continue;
                float4 v = sv[(((wm * 4 + sl) * 8) + n8) * 32 + lane];
                acc[n8][0] += v.x; acc[n8][1] += v.y;
                acc[n8][2] += v.z; acc[n8][3] += v.w;
            }
        }

        // ---- epilogue for owned n8 groups: xproj, exchange, gates, h store ----
        char* Hh = (char*)(&g_hfhi[cur ^ 1][mi][wm][ni][0][0]);
        char* Hl = (char*)(&g_hflo[cur ^ 1][mi][wm][ni][0][0]);
        #pragma unroll
        for (int j = 0; j < 2; j++) {
            const int n8 = 2 * kq + j;
            int ce = n8 * 8 + 2 * (lane & 3);
            int co = ce + 1;
            float wxe = swx[ce], wae = swa[ce], wye = swy[ce], bbe = sbb[ce];
            float wxo = swx[co], wao = swa[co], wyo = swy[co], bbo = sbb[co];
            acc[n8][0] += fmaf(wxe, x0, fmaf(wae, a0, fmaf(wye, y0, bbe)));
            acc[n8][1] += fmaf(wxo, x0, fmaf(wao, a0, fmaf(wyo, y0, bbo)));
            acc[n8][2] += fmaf(wxe, x1, fmaf(wae, a1, fmaf(wye, y1, bbe)));
            acc[n8][3] += fmaf(wxo, x1, fmaf(wao, a1, fmaf(wyo, y1, bbo)));

            float gg[4];
            #pragma unroll
            for (int i = 0; i < 4; i++)
                gg[i] = __shfl_xor_sync(0xffffffffu, acc[n8][i], 1);

            if (act) {
                const int flane = qr * 4 + (n8 & 3);
                const int regbase = 2 * (n8 >> 2);
                #pragma unroll
                for (int rr = 0; rr < 2; rr++) {
                    float iv = acc[n8][2 * rr + 0];
                    float fv = acc[n8][2 * rr + 1];
                    float gv = gg[2 * rr + 0];
                    float ov = gg[2 * rr + 1];
                    float cn = sigf(fv) * cst[j][rr] + sigf(iv) * tanh_fast(gv);
                    cst[j][rr] = cn;
                    float h = sigf(ov) * tanh_fast(cn);
                    unsigned off = (unsigned)(flane * 16 + (regbase + rr) * 4 + hb * 2);
                    __nv_bfloat16 hh = __float2bfloat16(h);
                    *(__nv_bfloat16*)(Hh + off) = hh;
                    *(__nv_bfloat16*)(Hl + off) =
                        __float2bfloat16(h - __bfloat162float(hh));
                    if (s == T_STEPS - 1) {
                        int kg = ni * UNITS + 2 * n8 + hb;
                        int bg = rr ? b1g : b0g;
                        g_hplain[bg * HID + kg] = h;
                    }
                }
            }
        }
        gsyncG(mi, ni, ++gep, tid, lane);
        cur ^= 1;
    }

    // all four groups done before heads read full h
    arrive_wait(&g_fcnt, 128u, tid, lane);

    const int b = tid;

    // Phase A: zx columns (blocks 0..63), ze logits (blocks 64..79)
    if (b < BATCH) {
        if (bid < 64) {
            const int m = bid;
            float acc = b_xi[m];
            const float* wm_ = W_xi + m * HID;
            #pragma unroll 8
            for (int k = 0; k < HID; k++)
                acc = fmaf(g_hplain[b * HID + k], __ldg(&wm_[k]), acc);
            out[b * 64 + m] = acc;                  // zx: [B][64] at 0
            g_zxT[m * BATCH + b] = acc;
        } else if (bid < 80) {
            const int e = bid - 64;
            float acc = b_eta[e];
            const float* we = W_eta + e * HID;
            #pragma unroll 8
            for (int k = 0; k < HID; k++)
                acc = fmaf(g_hplain[b * HID + k], __ldg(&we[k]), acc);
            g_zeT[e * BATCH + b] = acc;
        }
    }
    arrive_wait(&g_fcnt, 256u, tid, lane);

    // Phase B: zy columns (blocks 0..63), ze softmax (block 64)
    if (b < BATCH) {
        if (bid < 64) {
            const int m = bid;
            float acc = b_zeta[m];
            const float* wz = W_zeta + m * (HID + 64);
            #pragma unroll 8
            for (int k = 0; k < HID; k++)
                acc = fmaf(g_hplain[b * HID + k], __ldg(&wz[k]), acc);
            #pragma unroll
            for (int j = 0; j < 64; j++)
                acc = fmaf(g_zxT[j * BATCH + b], __ldg(&wz[HID + j]), acc);
            out[16384 + b * 64 + m] = acc;          // zy: [B][64] at 16384
        } else if (bid == 64) {
            float l[16];
            float mx = -1e30f;
            #pragma unroll
            for (int e = 0; e < 16; e++) {
                l[e] = g_zeT[e * BATCH + b];
                mx = fmaxf(mx, l[e]);
            }
            float ssum = 0.0f;
            #pragma unroll
            for (int e = 0; e < 16; e++) { l[e] = __expf(l[e] - mx); ssum += l[e]; }
            float inv = __fdividef(1.0f, ssum);
            #pragma unroll
            for (int e = 0; e < 16; e++)
                out[32768 + b * 16 + e] = l[e] * inv;   // ze: [B][16] at 32768
        }
    }
}

// Reset barrier counters after each run so graph replays start from zero.
extern "C" __global__ void reset_counters() {
    int i = threadIdx.x;
    if (i < 512) ((unsigned int*)g_gc)[i] = 0u;
    if (i == 0) g_fcnt = 0u;
}

extern "C" void kernel_launch(void* const* d_in, const int* in_sizes, int n_in,
                              void* d_out, int out_size) {
    const float* x      = (const float*)d_in[0];
    const float* a      = (const float*)d_in[1];
    const float* y      = (const float*)d_in[2];
    const float* W_ih   = (const float*)d_in[3];
    const float* W_hh   = (const float*)d_in[4];
    const float* b_ih   = (const float*)d_in[5];
    const float* b_hh   = (const float*)d_in[6];
    const float* W_eta  = (const float*)d_in[7];
    const float* b_eta  = (const float*)d_in[8];
    const float* W_xi   = (const float*)d_in[9];
    const float* b_xi   = (const float*)d_in[10];
    const float* W_zeta = (const float*)d_in[11];
    const float* b_zeta = (const float*)d_in[12];

    cudaFuncSetAttribute(lstm_persist,
                         cudaFuncAttributeMaxDynamicSharedMemorySize, SMEM_TOTAL);
    lstm_persist<<<NBLK, THREADS, SMEM_TOTAL>>>(
        x, a, y, W_ih, W_hh, b_ih, b_hh,
        W_eta, b_eta, W_xi, b_xi, W_zeta, b_zeta,
        (float*)d_out);
    reset_counters<<<1, 512>>>();
}

// round 16
// speedup vs baseline: 1.2047x; 1.1504x over previous
#include <cuda_runtime.h>
#include <cuda_bf16.h>

#define T_STEPS 1024
#define BATCH   256
#define HID     512
#define NBLK    128
#define THREADS 512

// 2D tiling: 4 batch-slices x 32 unit-slices
#define MB       64      // batches per block
#define NG       64      // gate columns per block (16 units x 4 gates)
#define UNITS    16

// W smem (k-major, proven layout)
#define WPITCH    72                          // bf16 per k-row (64 + 8 pad) = 144 B
#define WBYTES    (HID * WPITCH * 2)          // 73728 per W matrix
#define OFF_WHI   0
#define OFF_WLO   WBYTES
#define OFF_P     (2 * WBYTES)                // 147456 (params, 1 KB)
#define OFF_R     (OFF_P + 1024)              // 148480 (reduction buffer)
#define RED_BYTES (4 * 4 * 8 * 32 * 16)       // 65536: [wm][slot][n8][lane] float4
#define SMEM_TOTAL (OFF_R + RED_BYTES)        // 214016

// h in MMA A-fragment layout, hi and lo split (proven r12-r15):
// [buf][mi][mt][kt][lane][8 bf16] -> 16B lane record; warp kt-load = 512B contig.
__device__ __nv_bfloat16 g_hfhi[2][4][4][32][32][8];   // 512 KB
__device__ __nv_bfloat16 g_hflo[2][4][4][32][32][8];   // 512 KB
__device__ float g_hplain[BATCH * HID];                // final h, fp32
__device__ float g_zxT[64 * BATCH];
__device__ float g_zeT[16 * BATCH];
// Leaf counters: g_gc[leaf][mi*32]; leaf = kt-range quarter (ni>>3 / kq).
__device__ unsigned int g_gc[4][128];
__device__ unsigned int g_fcnt;            // full-grid monotonic counter

// ---------- helpers ----------
__device__ __forceinline__ unsigned s2u(const void* p) {
    unsigned r;
    asm("{ .reg .u64 t; cvta.to.shared.u64 t, %1; cvt.u32.u64 %0, t; }"
        : "=r"(r) : "l"(p));
    return r;
}

__device__ __forceinline__ void mma16816(float* d, const unsigned* a, const unsigned* b) {
    asm volatile(
        "mma.sync.aligned.m16n8k16.row.col.f32.bf16.bf16.f32 "
        "{%0,%1,%2,%3}, {%4,%5,%6,%7}, {%8,%9}, {%0,%1,%2,%3};"
        : "+f"(d[0]), "+f"(d[1]), "+f"(d[2]), "+f"(d[3])
        : "r"(a[0]), "r"(a[1]), "r"(a[2]), "r"(a[3]), "r"(b[0]), "r"(b[1]));
}

__device__ __forceinline__ void ldsm_x4t(unsigned* r, unsigned addr) {
    asm volatile("ldmatrix.sync.aligned.m8n8.x4.trans.shared.b16 {%0,%1,%2,%3}, [%4];"
                 : "=r"(r[0]), "=r"(r[1]), "=r"(r[2]), "=r"(r[3]) : "r"(addr));
}

__device__ __forceinline__ float sigf(float v) {
    return __fdividef(1.0f, 1.0f + __expf(-v));
}
__device__ __forceinline__ float tanh_fast(float v) {
    return __fdividef(2.0f, 1.0f + __expf(-2.0f * v)) - 1.0f;
}

// Arrive at this block's leaf (kt-range) counter. No wait here.
__device__ __forceinline__ void arriveG(int mi, int ni, int tid) {
    __syncthreads();
    if (tid == 0) {
        __threadfence();
        asm volatile("red.release.gpu.global.add.u32 [%0], 1;"
                     :: "l"(&g_gc[ni >> 3][mi << 5]) : "memory");
    }
}

// Per-warp wait: this warp's GEMM only needs leaf kq's 8 producer blocks.
__device__ __forceinline__ void waitG(int mi, int kq, unsigned target, int lane) {
    if (lane == 0) {
        unsigned v;
        unsigned int* addr = &g_gc[kq][mi << 5];
        do {
            asm volatile("ld.acquire.gpu.global.u32 %0, [%1];"
                         : "=r"(v) : "l"(addr) : "memory");
        } while (v < target);
    }
    __syncwarp();
}

// Full-grid monotonic barrier (final phases only).
__device__ __forceinline__ void arrive_wait(unsigned int* cnt, unsigned target,
                                            int tid, int lane) {
    __syncthreads();
    if (tid == 0) {
        __threadfence();
        asm volatile("red.release.gpu.global.add.u32 [%0], 1;"
                     :: "l"(cnt) : "memory");
    }
    if (lane == 0) {
        unsigned v;
        do {
            asm volatile("ld.acquire.gpu.global.u32 %0, [%1];"
                         : "=r"(v) : "l"(cnt) : "memory");
        } while (v < target);
    }
    __syncwarp();
}

// ---------- main persistent kernel ----------
extern "C" __global__ void __launch_bounds__(THREADS, 1)
lstm_persist(const float* __restrict__ x, const float* __restrict__ a,
             const float* __restrict__ y,
             const float* __restrict__ W_ih, const float* __restrict__ W_hh,
             const float* __restrict__ b_ih, const float* __restrict__ b_hh,
             const float* __restrict__ W_eta, const float* __restrict__ b_eta,
             const float* __restrict__ W_xi,  const float* __restrict__ b_xi,
             const float* __restrict__ W_zeta, const float* __restrict__ b_zeta,
             float* __restrict__ out) {
    extern __shared__ char smem[];
    __nv_bfloat16* sWhi = (__nv_bfloat16*)(smem + OFF_WHI);
    __nv_bfloat16* sWlo = (__nv_bfloat16*)(smem + OFF_WLO);
    float* swx = (float*)(smem + OFF_P);
    float* swa = swx + 64;
    float* swy = swx + 128;
    float* sbb = swx + 192;
    float4* sv = (float4*)(smem + OFF_R);   // [wm][slot][n8][lane]
    const unsigned sb = s2u(smem);

    const int tid  = threadIdx.x;
    const int lane = tid & 31;
    const int w    = tid >> 5;       // 16 warps
    const int bid  = blockIdx.x;
    const int mi   = bid >> 5;       // batch slice 0..3
    const int ni   = bid & 31;       // unit slice 0..31
    const int wm   = w & 3;          // m-tile (== SMSP id)
    const int kq   = w >> 2;         // kt quarter 0..3 (owns n8 {2kq,2kq+1})

    unsigned gep = 0;

    // ---- W tile into smem, K-MAJOR (proven layout) ----
    for (int idx = tid; idx < NG * HID; idx += THREADS) {
        int j = idx >> 9, k = idx & 511;
        int row = (j & 3) * HID + ni * UNITS + (j >> 2);
        float v = W_hh[row * HID + k];
        __nv_bfloat16 hi = __float2bfloat16(v);
        sWhi[k * WPITCH + j] = hi;
        sWlo[k * WPITCH + j] = __float2bfloat16(v - __bfloat162float(hi));
    }
    if (tid < NG) {
        int row = (tid & 3) * HID + ni * UNITS + (tid >> 2);
        swx[tid] = W_ih[row * 3 + 0];
        swa[tid] = W_ih[row * 3 + 1];
        swy[tid] = W_ih[row * 3 + 2];
        sbb[tid] = b_ih[row] + b_hh[row];
    }

    // ---- zero OUR OWN fragment records in buffer 0 (kt = ni, all wm) ----
    // 2 arrays x 4 wm x 32 lanes x 16B = 4 KB; leaf arrival then carries
    // exactly the dependency consumers need.
    {
        uint4 z = make_uint4(0u, 0u, 0u, 0u);
        // layout: [buf][mi][wm][kt][lane][8] ; records for kt = ni
        for (int i = tid; i < 4 * 32; i += THREADS) {
            int wmi = i >> 5, ln = i & 31;
            *(uint4*)(&g_hfhi[0][mi][wmi][ni][ln][0]) = z;
            *(uint4*)(&g_hflo[0][mi][wmi][ni][ln][0]) = z;
        }
    }
    arriveG(mi, ni, tid);
    gep = 1;

    // epilogue ownership: warp (wm,kq) finalizes n8 in {2kq, 2kq+1};
    // within a lane pair, even lane handles rr=0, odd lane rr=1.
    const int rrl = lane & 1;
    const int qr  = lane >> 2;              // 0..7
    const int hb  = (lane & 3) >> 1;        // unit low bit (same within pair)
    const int r0  = 16 * wm + qr;
    const int b0g = mi * MB + r0;
    const int b1g = b0g + 8;
    const int bgl = rrl ? b1g : b0g;        // this lane's batch row
    float cst[2];
    cst[0] = cst[1] = 0.f;

    // B ldmatrix base
    const unsigned bbase = (unsigned)((lane & 15) * (WPITCH * 2)
                                      + ((lane >> 4) & 1) * 16);

    int cur = 0;
    for (int s = 0; s < T_STEPS; s++) {
        const int t = T_STEPS - 1 - s;

        // wait only for OUR kt-range producers (leaf kq), per warp
        waitG(mi, kq, 8u * gep, lane);

        // A fragments for this warp's kt quarter, straight from global.
        const uint4* Ah = (const uint4*)(&g_hfhi[cur][mi][wm][kq * 8][lane][0]);
        const uint4* Al = (const uint4*)(&g_hflo[cur][mi][wm][kq * 8][lane][0]);

        // depth-2 prefetch ring over 8 kt
        uint4 rh[2], rl[2];
        rh[0] = __ldcg(Ah);      rl[0] = __ldcg(Al);
        rh[1] = __ldcg(Ah + 32); rl[1] = __ldcg(Al + 32);

        float acc[8][4];
        #pragma unroll
        for (int i = 0; i < 8; i++)
            #pragma unroll
            for (int jj = 0; jj < 4; jj++) acc[i][jj] = 0.f;

        #pragma unroll
        for (int kl = 0; kl < 8; kl++) {
            const int kt = kq * 8 + kl;
            const int slot = kl & 1;
            unsigned ahi[4], alo[4];
            { uint4 v = rh[slot]; ahi[0]=v.x; ahi[1]=v.y; ahi[2]=v.z; ahi[3]=v.w; }
            { uint4 v = rl[slot]; alo[0]=v.x; alo[1]=v.y; alo[2]=v.z; alo[3]=v.w; }
            if (kl + 2 < 8) {
                rh[slot] = __ldcg(Ah + (kl + 2) * 32);
                rl[slot] = __ldcg(Al + (kl + 2) * 32);
            }

            const unsigned krow = (unsigned)(kt * (16 * WPITCH * 2));
            #pragma unroll
            for (int ng = 0; ng < 4; ng++) {
                unsigned bhi[4], blo[4];
                const unsigned boff = krow + bbase + (unsigned)(ng * 32);
                ldsm_x4t(bhi, sb + OFF_WHI + boff);
                ldsm_x4t(blo, sb + OFF_WLO + boff);
                mma16816(acc[2*ng],     ahi, bhi + 0);
                mma16816(acc[2*ng + 1], ahi, bhi + 2);
                mma16816(acc[2*ng],     ahi, blo + 0);
                mma16816(acc[2*ng + 1], ahi, blo + 2);
                mma16816(acc[2*ng],     alo, bhi + 0);
                mma16816(acc[2*ng + 1], alo, bhi + 2);
            }
        }

        // ---- all-warp reduction: publish non-owned n8 partials (6 STS.128) ----
        {
            float4* wslot = sv + ((wm * 4 + kq) * 8) * 32 + lane;
            #pragma unroll
            for (int n8 = 0; n8 < 8; n8++) {
                if ((n8 >> 1) == kq) continue;   // own groups stay in regs
                wslot[n8 * 32] =
                    make_float4(acc[n8][0], acc[n8][1], acc[n8][2], acc[n8][3]);
            }
        }

        // epilogue inputs loaded here (overlap the sync + fold latency)
        float x0 = __ldg(&x[t * BATCH + b0g]);
        float a0 = __ldg(&a[t * BATCH + b0g]);
        float y0 = __ldg(&y[t * BATCH + b0g]);
        float x1 = __ldg(&x[t * BATCH + b1g]);
        float a1 = __ldg(&a[t * BATCH + b1g]);
        float y1 = __ldg(&y[t * BATCH + b1g]);

        __syncthreads();

        // fold 3 other slots for our 2 owned n8 groups (6 LDS.128)
        #pragma unroll
        for (int j = 0; j < 2; j++) {
            const int n8 = 2 * kq + j;
            #pragma unroll
            for (int sl = 0; sl < 4; sl++) {
                if (sl == kq) continue;
                float4 v = sv[(((wm * 4 + sl) * 8) + n8) * 32 + lane];
                acc[n8][0] += v.x; acc[n8][1] += v.y;
                acc[n8][2] += v.z; acc[n8][3] += v.w;
            }
        }

        // ---- epilogue (parity-split): each lane computes ONE h per group ----
        char* Hh = (char*)(&g_hfhi[cur ^ 1][mi][wm][ni][0][0]);
        char* Hl = (char*)(&g_hflo[cur ^ 1][mi][wm][ni][0][0]);
        #pragma unroll
        for (int j = 0; j < 2; j++) {
            const int n8 = 2 * kq + j;
            int ce = n8 * 8 + 2 * (lane & 3);
            int co = ce + 1;
            float wxe = swx[ce], wae = swa[ce], wye = swy[ce], bbe = sbb[ce];
            float wxo = swx[co], wao = swa[co], wyo = swy[co], bbo = sbb[co];
            acc[n8][0] += fmaf(wxe, x0, fmaf(wae, a0, fmaf(wye, y0, bbe)));
            acc[n8][1] += fmaf(wxo, x0, fmaf(wao, a0, fmaf(wyo, y0, bbo)));
            acc[n8][2] += fmaf(wxe, x1, fmaf(wae, a1, fmaf(wye, y1, bbe)));
            acc[n8][3] += fmaf(wxo, x1, fmaf(wao, a1, fmaf(wyo, y1, bbo)));

            float g0 = __shfl_xor_sync(0xffffffffu, acc[n8][0], 1);
            float g1 = __shfl_xor_sync(0xffffffffu, acc[n8][1], 1);
            float g2 = __shfl_xor_sync(0xffffffffu, acc[n8][2], 1);
            float g3 = __shfl_xor_sync(0xffffffffu, acc[n8][3], 1);

            // even lane (rrl=0): i,f own acc[0..1]; g,o from partner (g0,g1)
            // odd  lane (rrl=1): i,f from partner (g2,g3); g,o own acc[2..3]
            float iv = rrl ? g2         : acc[n8][0];
            float fv = rrl ? g3         : acc[n8][1];
            float gv = rrl ? acc[n8][2] : g0;
            float ov = rrl ? acc[n8][3] : g1;

            float cn = sigf(fv) * cst[j] + sigf(iv) * tanh_fast(gv);
            cst[j] = cn;
            float h = sigf(ov) * tanh_fast(cn);

            const int flane = qr * 4 + (n8 & 3);
            const int regbase = 2 * (n8 >> 2);
            unsigned off = (unsigned)(flane * 16 + (regbase + rrl) * 4 + hb * 2);
            __nv_bfloat16 hh = __float2bfloat16(h);
            *(__nv_bfloat16*)(Hh + off) = hh;
            *(__nv_bfloat16*)(Hl + off) = __float2bfloat16(h - __bfloat162float(hh));
            if (s == T_STEPS - 1) {
                int kg = ni * UNITS + 2 * n8 + hb;
                g_hplain[bgl * HID + kg] = h;
            }
        }
        arriveG(mi, ni, tid);
        gep++;
        cur ^= 1;
    }

    // all four groups done before heads read full h
    arrive_wait(&g_fcnt, 128u, tid, lane);

    const int b = tid;

    // Phase A: zx columns (blocks 0..63), ze logits (blocks 64..79)
    if (b < BATCH) {
        if (bid < 64) {
            const int m = bid;
            float acc = b_xi[m];
            const float* wm_ = W_xi + m * HID;
            #pragma unroll 8
            for (int k = 0; k < HID; k++)
                acc = fmaf(g_hplain[b * HID + k], __ldg(&wm_[k]), acc);
            out[b * 64 + m] = acc;                  // zx: [B][64] at 0
            g_zxT[m * BATCH + b] = acc;
        } else if (bid < 80) {
            const int e = bid - 64;
            float acc = b_eta[e];
            const float* we = W_eta + e * HID;
            #pragma unroll 8
            for (int k = 0; k < HID; k++)
                acc = fmaf(g_hplain[b * HID + k], __ldg(&we[k]), acc);
            g_zeT[e * BATCH + b] = acc;
        }
    }
    arrive_wait(&g_fcnt, 256u, tid, lane);

    // Phase B: zy columns (blocks 0..63), ze softmax (block 64)
    if (b < BATCH) {
        if (bid < 64) {
            const int m = bid;
            float acc = b_zeta[m];
            const float* wz = W_zeta + m * (HID + 64);
            #pragma unroll 8
            for (int k = 0; k < HID; k++)
                acc = fmaf(g_hplain[b * HID + k], __ldg(&wz[k]), acc);
            #pragma unroll
            for (int j = 0; j < 64; j++)
                acc = fmaf(g_zxT[j * BATCH + b], __ldg(&wz[HID + j]), acc);
            out[16384 + b * 64 + m] = acc;          // zy: [B][64] at 16384
        } else if (bid == 64) {
            float l[16];
            float mx = -1e30f;
            #pragma unroll
            for (int e = 0; e < 16; e++) {
                l[e] = g_zeT[e * BATCH + b];
                mx = fmaxf(mx, l[e]);
            }
            float ssum = 0.0f;
            #pragma unroll
            for (int e = 0; e < 16; e++) { l[e] = __expf(l[e] - mx); ssum += l[e]; }
            float inv = __fdividef(1.0f, ssum);
            #pragma unroll
            for (int e = 0; e < 16; e++)
                out[32768 + b * 16 + e] = l[e] * inv;   // ze: [B][16] at 32768
        }
    }
}

// Reset barrier counters after each run so graph replays start from zero.
extern "C" __global__ void reset_counters() {
    int i = threadIdx.x;
    if (i < 512) ((unsigned int*)g_gc)[i] = 0u;
    if (i == 0) g_fcnt = 0u;
}

extern "C" void kernel_launch(void* const* d_in, const int* in_sizes, int n_in,
                              void* d_out, int out_size) {
    const float* x      = (const float*)d_in[0];
    const float* a      = (const float*)d_in[1];
    const float* y      = (const float*)d_in[2];
    const float* W_ih   = (const float*)d_in[3];
    const float* W_hh   = (const float*)d_in[4];
    const float* b_ih   = (const float*)d_in[5];
    const float* b_hh   = (const float*)d_in[6];
    const float* W_eta  = (const float*)d_in[7];
    const float* b_eta  = (const float*)d_in[8];
    const float* W_xi   = (const float*)d_in[9];
    const float* b_xi   = (const float*)d_in[10];
    const float* W_zeta = (const float*)d_in[11];
    const float* b_zeta = (const float*)d_in[12];

    cudaFuncSetAttribute(lstm_persist,
                         cudaFuncAttributeMaxDynamicSharedMemorySize, SMEM_TOTAL);
    lstm_persist<<<NBLK, THREADS, SMEM_TOTAL>>>(
        x, a, y, W_ih, W_hh, b_ih, b_hh,
        W_eta, b_eta, W_xi, b_xi, W_zeta, b_zeta,
        (float*)d_out);
    reset_counters<<<1, 512>>>();
}

// round 17
// speedup vs baseline: 1.2336x; 1.0240x over previous
#include <cuda_runtime.h>
#include <cuda_bf16.h>

#define T_STEPS 1024
#define BATCH   256
#define HID     512
#define NBLK    128
#define THREADS 512

// 2D tiling: 4 batch-slices x 32 unit-slices
#define MB       64      // batches per block
#define NG       64      // gate columns per block (16 units x 4 gates)
#define UNITS    16

// W smem (k-major, proven layout)
#define WPITCH    72                          // bf16 per k-row (64 + 8 pad) = 144 B
#define WBYTES    (HID * WPITCH * 2)          // 73728 per W matrix
#define OFF_WHI   0
#define OFF_WLO   WBYTES
#define OFF_P     (2 * WBYTES)                // 147456 (params, 1 KB)
#define OFF_R     (OFF_P + 1024)              // 148480 (reduction buffer)
#define RED_BYTES (4 * 4 * 8 * 32 * 16)       // 65536: [wm][slot][n8][lane] float4
#define SMEM_TOTAL (OFF_R + RED_BYTES)        // 214016

// h in MMA A-fragment layout, hi and lo split (proven r12-r16):
// [buf][mi][mt][kt][lane][8 bf16] -> 16B lane record; warp kt-load = 512B contig.
__device__ __nv_bfloat16 g_hfhi[2][4][4][32][32][8];   // 512 KB
__device__ __nv_bfloat16 g_hflo[2][4][4][32][32][8];   // 512 KB
__device__ float g_hplain[BATCH * HID];                // final h, fp32
__device__ float g_zxT[64 * BATCH];
__device__ float g_zeT[16 * BATCH];
// Per-wm-stream counters: g_gc2[wm][leaf][mi*32]; warp (wm,kq) of block ni
// arrives at [wm][ni>>3]; consumer (wm,kq) polls [wm][kq] (32 arrivals/epoch).
__device__ unsigned int g_gc2[4][4][128];
__device__ unsigned int g_fcnt;            // full-grid monotonic counter

// ---------- helpers ----------
__device__ __forceinline__ unsigned s2u(const void* p) {
    unsigned r;
    asm("{ .reg .u64 t; cvta.to.shared.u64 t, %1; cvt.u32.u64 %0, t; }"
        : "=r"(r) : "l"(p));
    return r;
}

__device__ __forceinline__ void mma16816(float* d, const unsigned* a, const unsigned* b) {
    asm volatile(
        "mma.sync.aligned.m16n8k16.row.col.f32.bf16.bf16.f32 "
        "{%0,%1,%2,%3}, {%4,%5,%6,%7}, {%8,%9}, {%0,%1,%2,%3};"
        : "+f"(d[0]), "+f"(d[1]), "+f"(d[2]), "+f"(d[3])
        : "r"(a[0]), "r"(a[1]), "r"(a[2]), "r"(a[3]), "r"(b[0]), "r"(b[1]));
}

__device__ __forceinline__ void ldsm_x4t(unsigned* r, unsigned addr) {
    asm volatile("ldmatrix.sync.aligned.m8n8.x4.trans.shared.b16 {%0,%1,%2,%3}, [%4];"
                 : "=r"(r[0]), "=r"(r[1]), "=r"(r[2]), "=r"(r[3]) : "r"(addr));
}

__device__ __forceinline__ float sigf(float v) {
    return __fdividef(1.0f, 1.0f + __expf(-v));
}
__device__ __forceinline__ float tanh_fast(float v) {
    return __fdividef(2.0f, 1.0f + __expf(-2.0f * v)) - 1.0f;
}

__device__ __forceinline__ void barwm(int id) {
    asm volatile("bar.sync %0, 128;" :: "r"(id) : "memory");
}

// Per-warp arrival: this warp's h-records for this step are published.
__device__ __forceinline__ void arriveW(int mi, int ni, int wm, int lane) {
    __syncwarp();
    if (lane == 0) {
        __threadfence();
        asm volatile("red.release.gpu.global.add.u32 [%0], 1;"
                     :: "l"(&g_gc2[wm][ni >> 3][mi << 5]) : "memory");
    }
}

// Per-warp wait: warp (wm,kq) needs the (wm,*) warps of leaf kq's 8 blocks.
__device__ __forceinline__ void waitW(int mi, int wm, int kq,
                                      unsigned target, int lane) {
    if (lane == 0) {
        unsigned v;
        unsigned int* addr = &g_gc2[wm][kq][mi << 5];
        do {
            asm volatile("ld.acquire.gpu.global.u32 %0, [%1];"
                         : "=r"(v) : "l"(addr) : "memory");
        } while (v < target);
    }
    __syncwarp();
}

// Full-grid monotonic barrier (final phases only).
__device__ __forceinline__ void arrive_wait(unsigned int* cnt, unsigned target,
                                            int tid, int lane) {
    __syncthreads();
    if (tid == 0) {
        __threadfence();
        asm volatile("red.release.gpu.global.add.u32 [%0], 1;"
                     :: "l"(cnt) : "memory");
    }
    if (lane == 0) {
        unsigned v;
        do {
            asm volatile("ld.acquire.gpu.global.u32 %0, [%1];"
                         : "=r"(v) : "l"(cnt) : "memory");
        } while (v < target);
    }
    __syncwarp();
}

// ---------- main persistent kernel ----------
extern "C" __global__ void __launch_bounds__(THREADS, 1)
lstm_persist(const float* __restrict__ x, const float* __restrict__ a,
             const float* __restrict__ y,
             const float* __restrict__ W_ih, const float* __restrict__ W_hh,
             const float* __restrict__ b_ih, const float* __restrict__ b_hh,
             const float* __restrict__ W_eta, const float* __restrict__ b_eta,
             const float* __restrict__ W_xi,  const float* __restrict__ b_xi,
             const float* __restrict__ W_zeta, const float* __restrict__ b_zeta,
             float* __restrict__ out) {
    extern __shared__ char smem[];
    __nv_bfloat16* sWhi = (__nv_bfloat16*)(smem + OFF_WHI);
    __nv_bfloat16* sWlo = (__nv_bfloat16*)(smem + OFF_WLO);
    float* swx = (float*)(smem + OFF_P);
    float* swa = swx + 64;
    float* swy = swx + 128;
    float* sbb = swx + 192;
    float4* sv = (float4*)(smem + OFF_R);   // [wm][slot][n8][lane]
    const unsigned sb = s2u(smem);

    const int tid  = threadIdx.x;
    const int lane = tid & 31;
    const int w    = tid >> 5;       // 16 warps
    const int bid  = blockIdx.x;
    const int mi   = bid >> 5;       // batch slice 0..3
    const int ni   = bid & 31;       // unit slice 0..31
    const int wm   = w & 3;          // m-tile (== SMSP id; wm-stream id)
    const int kq   = w >> 2;         // kt quarter 0..3 (owns n8 {2kq,2kq+1})

    unsigned gep = 0;

    // ---- W tile into smem, K-MAJOR (proven layout) ----
    for (int idx = tid; idx < NG * HID; idx += THREADS) {
        int j = idx >> 9, k = idx & 511;
        int row = (j & 3) * HID + ni * UNITS + (j >> 2);
        float v = W_hh[row * HID + k];
        __nv_bfloat16 hi = __float2bfloat16(v);
        sWhi[k * WPITCH + j] = hi;
        sWlo[k * WPITCH + j] = __float2bfloat16(v - __bfloat162float(hi));
    }
    if (tid < NG) {
        int row = (tid & 3) * HID + ni * UNITS + (tid >> 2);
        swx[tid] = W_ih[row * 3 + 0];
        swa[tid] = W_ih[row * 3 + 1];
        swy[tid] = W_ih[row * 3 + 2];
        sbb[tid] = b_ih[row] + b_hh[row];
    }

    // ---- zero OUR OWN fragment records in buffer 0 (kt = ni, all wm) ----
    {
        uint4 z = make_uint4(0u, 0u, 0u, 0u);
        for (int i = tid; i < 4 * 32; i += THREADS) {
            int wmi = i >> 5, ln = i & 31;
            *(uint4*)(&g_hfhi[0][mi][wmi][ni][ln][0]) = z;
            *(uint4*)(&g_hflo[0][mi][wmi][ni][ln][0]) = z;
        }
    }
    __syncthreads();               // zero-init complete block-wide
    arriveW(mi, ni, wm, lane);     // each warp signals its wm-stream
    gep = 1;

    // epilogue ownership: warp (wm,kq) finalizes n8 in {2kq, 2kq+1};
    // within a lane pair, even lane handles rr=0, odd lane rr=1.
    const int rrl = lane & 1;
    const int qr  = lane >> 2;              // 0..7
    const int hb  = (lane & 3) >> 1;        // unit low bit (same within pair)
    const int r0  = 16 * wm + qr;
    const int b0g = mi * MB + r0;
    const int b1g = b0g + 8;
    const int bgl = rrl ? b1g : b0g;        // this lane's batch row
    float cst[2];
    cst[0] = cst[1] = 0.f;

    // B ldmatrix base
    const unsigned bbase = (unsigned)((lane & 15) * (WPITCH * 2)
                                      + ((lane >> 4) & 1) * 16);

    int cur = 0;
    for (int s = 0; s < T_STEPS; s++) {
        const int t = T_STEPS - 1 - s;

        // wait only for OUR wm-stream's kt-range producers
        waitW(mi, wm, kq, 32u * gep, lane);

        // A fragments for this warp's kt quarter, straight from global.
        const uint4* Ah = (const uint4*)(&g_hfhi[cur][mi][wm][kq * 8][lane][0]);
        const uint4* Al = (const uint4*)(&g_hflo[cur][mi][wm][kq * 8][lane][0]);

        // depth-2 prefetch ring over 8 kt
        uint4 rh[2], rl[2];
        rh[0] = __ldcg(Ah);      rl[0] = __ldcg(Al);
        rh[1] = __ldcg(Ah + 32); rl[1] = __ldcg(Al + 32);

        float acc[8][4];
        #pragma unroll
        for (int i = 0; i < 8; i++)
            #pragma unroll
            for (int jj = 0; jj < 4; jj++) acc[i][jj] = 0.f;

        #pragma unroll
        for (int kl = 0; kl < 8; kl++) {
            const int kt = kq * 8 + kl;
            const int slot = kl & 1;
            unsigned ahi[4], alo[4];
            { uint4 v = rh[slot]; ahi[0]=v.x; ahi[1]=v.y; ahi[2]=v.z; ahi[3]=v.w; }
            { uint4 v = rl[slot]; alo[0]=v.x; alo[1]=v.y; alo[2]=v.z; alo[3]=v.w; }
            if (kl + 2 < 8) {
                rh[slot] = __ldcg(Ah + (kl + 2) * 32);
                rl[slot] = __ldcg(Al + (kl + 2) * 32);
            }

            const unsigned krow = (unsigned)(kt * (16 * WPITCH * 2));
            #pragma unroll
            for (int ng = 0; ng < 4; ng++) {
                unsigned bhi[4], blo[4];
                const unsigned boff = krow + bbase + (unsigned)(ng * 32);
                ldsm_x4t(bhi, sb + OFF_WHI + boff);
                ldsm_x4t(blo, sb + OFF_WLO + boff);
                mma16816(acc[2*ng],     ahi, bhi + 0);
                mma16816(acc[2*ng + 1], ahi, bhi + 2);
                mma16816(acc[2*ng],     ahi, blo + 0);
                mma16816(acc[2*ng + 1], ahi, blo + 2);
                mma16816(acc[2*ng],     alo, bhi + 0);
                mma16816(acc[2*ng + 1], alo, bhi + 2);
            }
        }

        // ---- publish non-owned n8 partials (6 STS.128, wm-local slots) ----
        {
            float4* wslot = sv + ((wm * 4 + kq) * 8) * 32 + lane;
            #pragma unroll
            for (int n8 = 0; n8 < 8; n8++) {
                if ((n8 >> 1) == kq) continue;   // own groups stay in regs
                wslot[n8 * 32] =
                    make_float4(acc[n8][0], acc[n8][1], acc[n8][2], acc[n8][3]);
            }
        }

        // epilogue inputs loaded here (overlap barrier + fold latency)
        float x0 = __ldg(&x[t * BATCH + b0g]);
        float a0 = __ldg(&a[t * BATCH + b0g]);
        float y0 = __ldg(&y[t * BATCH + b0g]);
        float x1 = __ldg(&x[t * BATCH + b1g]);
        float a1 = __ldg(&a[t * BATCH + b1g]);
        float y1 = __ldg(&y[t * BATCH + b1g]);

        barwm(1 + wm);   // publish visible within wm-group (4 warps, 1 SMSP)

        // fold 3 other slots for our 2 owned n8 groups (6 LDS.128)
        #pragma unroll
        for (int j = 0; j < 2; j++) {
            const int n8 = 2 * kq + j;
            #pragma unroll
            for (int sl = 0; sl < 4; sl++) {
                if (sl == kq) continue;
                float4 v = sv[(((wm * 4 + sl) * 8) + n8) * 32 + lane];
                acc[n8][0] += v.x; acc[n8][1] += v.y;
                acc[n8][2] += v.z; acc[n8][3] += v.w;
            }
        }

        barwm(5 + wm);   // folds complete before any sibling's next publish

        // ---- epilogue (parity-split): each lane computes ONE h per group ----
        char* Hh = (char*)(&g_hfhi[cur ^ 1][mi][wm][ni][0][0]);
        char* Hl = (char*)(&g_hflo[cur ^ 1][mi][wm][ni][0][0]);
        #pragma unroll
        for (int j = 0; j < 2; j++) {
            const int n8 = 2 * kq + j;
            int ce = n8 * 8 + 2 * (lane & 3);
            int co = ce + 1;
            float wxe = swx[ce], wae = swa[ce], wye = swy[ce], bbe = sbb[ce];
            float wxo = swx[co], wao = swa[co], wyo = swy[co], bbo = sbb[co];
            acc[n8][0] += fmaf(wxe, x0, fmaf(wae, a0, fmaf(wye, y0, bbe)));
            acc[n8][1] += fmaf(wxo, x0, fmaf(wao, a0, fmaf(wyo, y0, bbo)));
            acc[n8][2] += fmaf(wxe, x1, fmaf(wae, a1, fmaf(wye, y1, bbe)));
            acc[n8][3] += fmaf(wxo, x1, fmaf(wao, a1, fmaf(wyo, y1, bbo)));

            float g0 = __shfl_xor_sync(0xffffffffu, acc[n8][0], 1);
            float g1 = __shfl_xor_sync(0xffffffffu, acc[n8][1], 1);
            float g2 = __shfl_xor_sync(0xffffffffu, acc[n8][2], 1);
            float g3 = __shfl_xor_sync(0xffffffffu, acc[n8][3], 1);

            float iv = rrl ? g2         : acc[n8][0];
            float fv = rrl ? g3         : acc[n8][1];
            float gv = rrl ? acc[n8][2] : g0;
            float ov = rrl ? acc[n8][3] : g1;

            float cn = sigf(fv) * cst[j] + sigf(iv) * tanh_fast(gv);
            cst[j] = cn;
            float h = sigf(ov) * tanh_fast(cn);

            const int flane = qr * 4 + (n8 & 3);
            const int regbase = 2 * (n8 >> 2);
            unsigned off = (unsigned)(flane * 16 + (regbase + rrl) * 4 + hb * 2);
            __nv_bfloat16 hh = __float2bfloat16(h);
            *(__nv_bfloat16*)(Hh + off) = hh;
            *(__nv_bfloat16*)(Hl + off) = __float2bfloat16(h - __bfloat162float(hh));
            if (s == T_STEPS - 1) {
                int kg = ni * UNITS + 2 * n8 + hb;
                g_hplain[bgl * HID + kg] = h;
            }
        }
        arriveW(mi, ni, wm, lane);
        gep++;
        cur ^= 1;
    }

    // all groups done before heads read full h
    arrive_wait(&g_fcnt, 128u, tid, lane);

    const int b = tid;

    // Phase A: zx columns (blocks 0..63), ze logits (blocks 64..79)
    if (b < BATCH) {
        if (bid < 64) {
            const int m = bid;
            float acc = b_xi[m];
            const float* wm_ = W_xi + m * HID;
            #pragma unroll 8
            for (int k = 0; k < HID; k++)
                acc = fmaf(g_hplain[b * HID + k], __ldg(&wm_[k]), acc);
            out[b * 64 + m] = acc;                  // zx: [B][64] at 0
            g_zxT[m * BATCH + b] = acc;
        } else if (bid < 80) {
            const int e = bid - 64;
            float acc = b_eta[e];
            const float* we = W_eta + e * HID;
            #pragma unroll 8
            for (int k = 0; k < HID; k++)
                acc = fmaf(g_hplain[b * HID + k], __ldg(&we[k]), acc);
            g_zeT[e * BATCH + b] = acc;
        }
    }
    arrive_wait(&g_fcnt, 256u, tid, lane);

    // Phase B: zy columns (blocks 0..63), ze softmax (block 64)
    if (b < BATCH) {
        if (bid < 64) {
            const int m = bid;
            float acc = b_zeta[m];
            const float* wz = W_zeta + m * (HID + 64);
            #pragma unroll 8
            for (int k = 0; k < HID; k++)
                acc = fmaf(g_hplain[b * HID + k], __ldg(&wz[k]), acc);
            #pragma unroll
            for (int j = 0; j < 64; j++)
                acc = fmaf(g_zxT[j * BATCH + b], __ldg(&wz[HID + j]), acc);
            out[16384 + b * 64 + m] = acc;          // zy: [B][64] at 16384
        } else if (bid == 64) {
            float l[16];
            float mx = -1e30f;
            #pragma unroll
            for (int e = 0; e < 16; e++) {
                l[e] = g_zeT[e * BATCH + b];
                mx = fmaxf(mx, l[e]);
            }
            float ssum = 0.0f;
            #pragma unroll
            for (int e = 0; e < 16; e++) { l[e] = __expf(l[e] - mx); ssum += l[e]; }
            float inv = __fdividef(1.0f, ssum);
            #pragma unroll
            for (int e = 0; e < 16; e++)
                out[32768 + b * 16 + e] = l[e] * inv;   // ze: [B][16] at 32768
        }
    }
}

// Reset barrier counters after each run so graph replays start from zero.
extern "C" __global__ void reset_counters() {
    int i = threadIdx.x + blockDim.x * 0;
    for (int k = i; k < 4 * 4 * 128; k += 1024) ((unsigned int*)g_gc2)[k] = 0u;
    if (i == 0) g_fcnt = 0u;
}

extern "C" void kernel_launch(void* const* d_in, const int* in_sizes, int n_in,
                              void* d_out, int out_size) {
    const float* x      = (const float*)d_in[0];
    const float* a      = (const float*)d_in[1];
    const float* y      = (const float*)d_in[2];
    const float* W_ih   = (const float*)d_in[3];
    const float* W_hh   = (const float*)d_in[4];
    const float* b_ih   = (const float*)d_in[5];
    const float* b_hh   = (const float*)d_in[6];
    const float* W_eta  = (const float*)d_in[7];
    const float* b_eta  = (const float*)d_in[8];
    const float* W_xi   = (const float*)d_in[9];
    const float* b_xi   = (const float*)d_in[10];
    const float* W_zeta = (const float*)d_in[11];
    const float* b_zeta = (const float*)d_in[12];

    cudaFuncSetAttribute(lstm_persist,
                         cudaFuncAttributeMaxDynamicSharedMemorySize, SMEM_TOTAL);
    lstm_persist<<<NBLK, THREADS, SMEM_TOTAL>>>(
        x, a, y, W_ih, W_hh, b_ih, b_hh,
        W_eta, b_eta, W_xi, b_xi, W_zeta, b_zeta,
        (float*)d_out);
    reset_counters<<<1, 1024>>>();
}